// round 1
// baseline (speedup 1.0000x reference)
#include <cuda_runtime.h>
#include <cstdint>
#include <math.h>

#define NEURONS 4096
#define HIST    64
#define MID     128
#define BATCH   1024
#define TILE_M  128

#define XS_STRIDE  68   // 68 mod 32 = 4 -> A-frag LDS conflict-free
#define W1S_STRIDE 136  // 136 mod 32 = 8 -> B-frag LDS conflict-free

__device__ __forceinline__ uint32_t f2tf32(float f) {
    uint32_t r;
    asm("cvt.rna.tf32.f32 %0, %1;" : "=r"(r) : "f"(f));
    return r;
}

__device__ __forceinline__ float gelu_exact(float v) {
    return 0.5f * v * (1.0f + erff(v * 0.70710678118654752f));
}

extern "C" __global__ void __launch_bounds__(256, 2)
neuron_mlp_kernel(const float* __restrict__ x,
                  const float* __restrict__ w1,
                  const float* __restrict__ w2,
                  float* __restrict__ out)
{
    extern __shared__ unsigned char smem_raw[];
    uint32_t* Xs  = (uint32_t*)smem_raw;                 // [128][68]  tf32 bits
    uint32_t* W1s = Xs + TILE_M * XS_STRIDE;             // [64][136]  tf32 bits
    float*    W2s = (float*)(W1s + HIST * W1S_STRIDE);   // [128]
    float*    red = W2s + MID;                           // [2][128]

    const int tid = threadIdx.x;
    const int n   = blockIdx.y;
    const int b0  = blockIdx.x * TILE_M;

    // ---- load X tile [128 x 64] (f32 -> tf32), 64B contiguous per row per instr ----
    {
        const int q  = tid & 3;        // quarter within row
        const int r0 = tid >> 2;       // 0..63
        #pragma unroll
        for (int half = 0; half < 2; ++half) {
            const int row = r0 + half * 64;
            const float4* src = (const float4*)(x + (size_t)(b0 + row) * (NEURONS * HIST)
                                                  + (size_t)n * HIST);
            uint32_t* dst = Xs + row * XS_STRIDE;
            #pragma unroll
            for (int i = 0; i < 4; ++i) {
                float4 v = src[i * 4 + q];
                int c = (i * 4 + q) * 4;
                dst[c + 0] = f2tf32(v.x); dst[c + 1] = f2tf32(v.y);
                dst[c + 2] = f2tf32(v.z); dst[c + 3] = f2tf32(v.w);
            }
        }
    }
    // ---- load W1 tile [64 x 128] (contiguous 32KB) ----
    {
        const int q   = tid & 3;
        const int row = tid >> 2;      // 0..63
        const float4* src = (const float4*)(w1 + (size_t)n * (HIST * MID) + (size_t)row * MID);
        uint32_t* dst = W1s + row * W1S_STRIDE;
        #pragma unroll
        for (int i = 0; i < 8; ++i) {
            float4 v = src[i * 4 + q];
            int c = (i * 4 + q) * 4;
            dst[c + 0] = f2tf32(v.x); dst[c + 1] = f2tf32(v.y);
            dst[c + 2] = f2tf32(v.z); dst[c + 3] = f2tf32(v.w);
        }
    }
    if (tid < MID) W2s[tid] = w2[(size_t)n * MID + tid];
    __syncthreads();

    const int warp   = tid >> 5;
    const int lane   = tid & 31;
    const int warp_m = warp & 3;   // 4 warps along M (32 rows each)
    const int warp_n = warp >> 2;  // 2 warps along N (64 cols each)
    const int r = lane >> 2;
    const int q = lane & 3;

    float acc[2][8][4];
    #pragma unroll
    for (int mt = 0; mt < 2; ++mt)
        #pragma unroll
        for (int nt = 0; nt < 8; ++nt)
            #pragma unroll
            for (int j = 0; j < 4; ++j) acc[mt][nt][j] = 0.f;

    #pragma unroll
    for (int k = 0; k < 8; ++k) {
        const int kk = k * 8;
        uint32_t a[2][4];
        #pragma unroll
        for (int mt = 0; mt < 2; ++mt) {
            const int m0 = warp_m * 32 + mt * 16;
            a[mt][0] = Xs[(m0 + r)     * XS_STRIDE + kk + q];
            a[mt][1] = Xs[(m0 + r + 8) * XS_STRIDE + kk + q];
            a[mt][2] = Xs[(m0 + r)     * XS_STRIDE + kk + q + 4];
            a[mt][3] = Xs[(m0 + r + 8) * XS_STRIDE + kk + q + 4];
        }
        uint32_t b[8][2];
        #pragma unroll
        for (int nt = 0; nt < 8; ++nt) {
            const int n0 = warp_n * 64 + nt * 8;
            b[nt][0] = W1s[(kk + q)     * W1S_STRIDE + n0 + r];
            b[nt][1] = W1s[(kk + q + 4) * W1S_STRIDE + n0 + r];
        }
        #pragma unroll
        for (int mt = 0; mt < 2; ++mt)
            #pragma unroll
            for (int nt = 0; nt < 8; ++nt) {
                asm volatile(
                    "mma.sync.aligned.m16n8k8.row.col.f32.tf32.tf32.f32 "
                    "{%0,%1,%2,%3}, {%4,%5,%6,%7}, {%8,%9}, {%0,%1,%2,%3};"
                    : "+f"(acc[mt][nt][0]), "+f"(acc[mt][nt][1]),
                      "+f"(acc[mt][nt][2]), "+f"(acc[mt][nt][3])
                    : "r"(a[mt][0]), "r"(a[mt][1]), "r"(a[mt][2]), "r"(a[mt][3]),
                      "r"(b[nt][0]), "r"(b[nt][1]));
            }
    }

    // ---- epilogue: exact GELU, fold w2, reduce over MID ----
    #pragma unroll
    for (int mt = 0; mt < 2; ++mt) {
        float s0 = 0.f, s1 = 0.f;
        #pragma unroll
        for (int nt = 0; nt < 8; ++nt) {
            const int col0 = warp_n * 64 + nt * 8 + 2 * q;
            const float w2a = W2s[col0], w2b = W2s[col0 + 1];
            s0 += gelu_exact(acc[mt][nt][0]) * w2a + gelu_exact(acc[mt][nt][1]) * w2b;
            s1 += gelu_exact(acc[mt][nt][2]) * w2a + gelu_exact(acc[mt][nt][3]) * w2b;
        }
        // reduce across the 4 lanes (q = lane&3) that share a row
        s0 += __shfl_xor_sync(0xffffffffu, s0, 1);
        s0 += __shfl_xor_sync(0xffffffffu, s0, 2);
        s1 += __shfl_xor_sync(0xffffffffu, s1, 1);
        s1 += __shfl_xor_sync(0xffffffffu, s1, 2);
        if (q == 0) {
            const int row0 = warp_m * 32 + mt * 16 + r;
            red[warp_n * TILE_M + row0]     = s0;
            red[warp_n * TILE_M + row0 + 8] = s1;
        }
    }
    __syncthreads();
    if (tid < TILE_M) {
        out[(size_t)(b0 + tid) * NEURONS + n] = red[tid] + red[TILE_M + tid];
    }
}

extern "C" void kernel_launch(void* const* d_in, const int* in_sizes, int n_in,
                              void* d_out, int out_size) {
    const float* x  = (const float*)d_in[0];
    const float* w1 = (const float*)d_in[1];
    const float* w2 = (const float*)d_in[2];
    float* out = (float*)d_out;

    const size_t smem = (size_t)(TILE_M * XS_STRIDE + HIST * W1S_STRIDE) * 4
                      + (size_t)(MID + 2 * TILE_M) * 4;   // 71168 B
    cudaFuncSetAttribute(neuron_mlp_kernel,
                         cudaFuncAttributeMaxDynamicSharedMemorySize, (int)smem);

    dim3 grid(BATCH / TILE_M, NEURONS);
    neuron_mlp_kernel<<<grid, 256, smem>>>(x, w1, w2, out);
}